// round 13
// baseline (speedup 1.0000x reference)
#include <cuda_runtime.h>
#include <cuda_bf16.h>

#define BB 64
#define NN 2048
#define DD 256
#define EPS 1e-05f

#define CHUNKS 32
#define ROWS_PER_CHUNK (NN / CHUNKS)   // 64
#define ROWS_PER_NORM 16
#define NPARTS (NN / ROWS_PER_NORM)    // 128 norm blocks per batch
#define STATS_BLOCKS (BB * CHUNKS)     // 2048
#define FLAG_DONE (CHUNKS + 1)         // 33

// Owned-slot partials: no zeroing, no data races.
__device__ float2 g_partial[BB * CHUNKS];
__device__ float2 g_mi[BB];
// Protocol counters. Static-init 0; each launch restores them to 0 -> graph-safe.
__device__ unsigned int g_count[BB];
__device__ unsigned int g_done[BB];

__global__ __launch_bounds__(256) void fused_kernel(const float* __restrict__ x,
                                                    const int* __restrict__ lengths,
                                                    const float* __restrict__ weights,
                                                    const float* __restrict__ biases,
                                                    float* __restrict__ out) {
    const int bid = blockIdx.x;
    float4* __restrict__ op = reinterpret_cast<float4*>(out);
    const float4 z = make_float4(0.0f, 0.0f, 0.0f, 0.0f);

    if (bid < STATS_BLOCKS) {
        // ------- Stats phase: read valid rows + zero-fill invalid rows -------
        // Reads and writes stream concurrently (opposite HBM directions).
        const int b = bid >> 5;       // batch
        const int chunk = bid & 31;
        const int len = lengths[b];
        const int row0 = chunk * ROWS_PER_CHUNK;
        const int row_end = row0 + ROWS_PER_CHUNK;
        const int vend = min(row_end, len);   // valid end within this chunk

        float s0 = 0.f, s1 = 0.f, s2 = 0.f, s3 = 0.f;
        float q0 = 0.f, q1 = 0.f, q2 = 0.f, q3 = 0.f;
        if (vend > row0) {
            const float4* __restrict__ p =
                reinterpret_cast<const float4*>(x + (size_t)b * NN * DD) + (size_t)row0 * (DD / 4);
            const int nvec = (vend - row0) * (DD / 4);
            int i = threadIdx.x;
            for (; i + 768 < nvec; i += 1024) {
                float4 a  = p[i];
                float4 v1 = p[i + 256];
                float4 v2 = p[i + 512];
                float4 v3 = p[i + 768];
                s0 += (a.x + a.y) + (a.z + a.w);
                q0 += a.x * a.x + a.y * a.y + a.z * a.z + a.w * a.w;
                s1 += (v1.x + v1.y) + (v1.z + v1.w);
                q1 += v1.x * v1.x + v1.y * v1.y + v1.z * v1.z + v1.w * v1.w;
                s2 += (v2.x + v2.y) + (v2.z + v2.w);
                q2 += v2.x * v2.x + v2.y * v2.y + v2.z * v2.z + v2.w * v2.w;
                s3 += (v3.x + v3.y) + (v3.z + v3.w);
                q3 += v3.x * v3.x + v3.y * v3.y + v3.z * v3.z + v3.w * v3.w;
            }
            for (; i < nvec; i += 256) {
                float4 a = p[i];
                s0 += (a.x + a.y) + (a.z + a.w);
                q0 += a.x * a.x + a.y * a.y + a.z * a.z + a.w * a.w;
            }
        }
        float s  = (s0 + s1) + (s2 + s3);
        float ss = (q0 + q1) + (q2 + q3);

        #pragma unroll
        for (int off = 16; off > 0; off >>= 1) {
            s  += __shfl_xor_sync(0xFFFFFFFFu, s,  off);
            ss += __shfl_xor_sync(0xFFFFFFFFu, ss, off);
        }
        __shared__ float sh_s[8], sh_ss[8];
        const int wid = threadIdx.x >> 5;
        const int lid = threadIdx.x & 31;
        if (lid == 0) { sh_s[wid] = s; sh_ss[wid] = ss; }
        __syncthreads();
        if (wid == 0) {
            s  = (lid < 8) ? sh_s[lid]  : 0.0f;
            ss = (lid < 8) ? sh_ss[lid] : 0.0f;
            #pragma unroll
            for (int off = 4; off > 0; off >>= 1) {
                s  += __shfl_xor_sync(0xFFFFFFFFu, s,  off);
                ss += __shfl_xor_sync(0xFFFFFFFFu, ss, off);
            }
            if (lid == 0) {
                g_partial[b * CHUNKS + chunk] = make_float2(s, ss);
                __threadfence();
                const unsigned int old = atomicAdd(&g_count[b], 1u);
                if (old == CHUNKS - 1) {
                    __threadfence();
                    float fs = 0.0f, fss = 0.0f;
                    #pragma unroll
                    for (int i = 0; i < CHUNKS; i++) {
                        float2 p2 = __ldcg(&g_partial[b * CHUNKS + i]);
                        fs += p2.x; fss += p2.y;
                    }
                    const float denom = (float)len * (float)DD;
                    const float mean  = fs / denom;
                    const float var   = fmaxf(fss / denom - mean * mean, 0.0f);
                    g_mi[b] = make_float2(mean, 1.0f / (sqrtf(var) + EPS));
                    __threadfence();
                    atomicExch(&g_count[b], FLAG_DONE);  // release flag
                }
            }
        }

        // Zero-fill this chunk's invalid rows [max(row0, len), row_end).
        const int zstart = max(row0, vend);
        if (zstart < row_end) {
            float4* __restrict__ zp =
                op + (size_t)b * NN * (DD / 4) + (size_t)zstart * (DD / 4);
            const int nz = (row_end - zstart) * (DD / 4);
            for (int i = threadIdx.x; i < nz; i += 256)
                __stcs(&zp[i], z);
        }
        return;
    }

    // ------- Norm phase: valid rows only (invalid region already zeroed) -------
    const int nb = bid - STATS_BLOCKS;
    const int b = nb >> 7;        // batch
    const int part = nb & (NPARTS - 1);
    const int len = lengths[b];
    const int base = part * ROWS_PER_NORM;
    const int r = base + (threadIdx.x >> 6);
    const int c = threadIdx.x & 63;

    if (base >= len) {  // fully invalid: nothing to do (stats phase zeroed it)
        if (threadIdx.x == 0) {
            const unsigned int d = atomicAdd(&g_done[b], 1u);
            if (d == NPARTS - 1) {            // last norm block: re-arm protocol
                atomicExch(&g_count[b], 0u);
                atomicExch(&g_done[b], 0u);
            }
        }
        return;
    }

    // Gate on this batch's stats.
    if (threadIdx.x == 0) {
        while (*(volatile unsigned int*)&g_count[b] != FLAG_DONE) __nanosleep(32);
        __threadfence();
    }
    __syncthreads();

    const size_t bidx = (size_t)b * NN * (DD / 4) + c;
    const float2 mi = __ldcg(&g_mi[b]);   // L2 read: avoid stale L1 line
    const float mean = mi.x, inv = mi.y;
    const float4 w  = reinterpret_cast<const float4*>(weights)[c];
    const float4 bi = reinterpret_cast<const float4*>(biases)[c];

    if (base + ROWS_PER_NORM <= len) {  // fully valid: no per-row checks
        #pragma unroll
        for (int k = 0; k < 4; k++) {
            const size_t idx = bidx + (size_t)(r + 4 * k) * (DD / 4);
            const float4 v = reinterpret_cast<const float4*>(x)[idx];
            float4 o;
            o.x = (v.x - mean) * inv * w.x + bi.x;
            o.y = (v.y - mean) * inv * w.y + bi.y;
            o.z = (v.z - mean) * inv * w.z + bi.z;
            o.w = (v.w - mean) * inv * w.w + bi.w;
            __stcs(&op[idx], o);
        }
    } else {
        // Mixed block: write valid rows only.
        #pragma unroll
        for (int k = 0; k < 4; k++) {
            const int row = r + 4 * k;
            if (row < len) {
                const size_t idx = bidx + (size_t)row * (DD / 4);
                const float4 v = reinterpret_cast<const float4*>(x)[idx];
                float4 o;
                o.x = (v.x - mean) * inv * w.x + bi.x;
                o.y = (v.y - mean) * inv * w.y + bi.y;
                o.z = (v.z - mean) * inv * w.z + bi.z;
                o.w = (v.w - mean) * inv * w.w + bi.w;
                __stcs(&op[idx], o);
            }
        }
    }

    if (threadIdx.x == 0) {
        const unsigned int d = atomicAdd(&g_done[b], 1u);
        if (d == NPARTS - 1) {                // last norm block: re-arm protocol
            atomicExch(&g_count[b], 0u);
            atomicExch(&g_done[b], 0u);
        }
    }
}

extern "C" void kernel_launch(void* const* d_in, const int* in_sizes, int n_in,
                              void* d_out, int out_size) {
    const float* x        = (const float*)d_in[0];
    const int*   lengths  = (const int*)d_in[1];
    const float* weights  = (const float*)d_in[2];
    const float* biases   = (const float*)d_in[3];
    float* out = (float*)d_out;

    fused_kernel<<<STATS_BLOCKS + BB * NPARTS, 256>>>(x, lengths, weights, biases, out);
}

// round 14
// speedup vs baseline: 1.0384x; 1.0384x over previous
#include <cuda_runtime.h>
#include <cuda_bf16.h>

#define BB 64
#define NN 2048
#define DD 256
#define EPS 1e-05f

#define CHUNKS 32
#define ROWS_PER_CHUNK (NN / CHUNKS)   // 64
#define ROWS_PER_NORM 16
#define NPARTS (NN / ROWS_PER_NORM)    // 128 norm blocks per batch
#define STATS_BLOCKS (BB * CHUNKS)     // 2048
#define FLAG_DONE (CHUNKS + 1)         // 33

// Owned-slot partials: no zeroing, no data races.
__device__ float2 g_partial[BB * CHUNKS];
__device__ float2 g_mi[BB];
// Protocol counters. Static-init 0; each launch restores them to 0 -> graph-safe.
__device__ unsigned int g_count[BB];
__device__ unsigned int g_done[BB];

__global__ __launch_bounds__(256) void fused_kernel(const float* __restrict__ x,
                                                    const int* __restrict__ lengths,
                                                    const float* __restrict__ weights,
                                                    const float* __restrict__ biases,
                                                    float* __restrict__ out) {
    const int bid = blockIdx.x;

    if (bid < STATS_BLOCKS) {
        // ---------------- Stats phase ----------------
        const int b = bid >> 5;       // batch
        const int chunk = bid & 31;
        const int len = lengths[b];
        const int row0 = chunk * ROWS_PER_CHUNK;
        const int row1 = min(row0 + ROWS_PER_CHUNK, len);

        float s0 = 0.f, s1 = 0.f, s2 = 0.f, s3 = 0.f;
        float q0 = 0.f, q1 = 0.f, q2 = 0.f, q3 = 0.f;
        if (row1 > row0) {
            const float4* __restrict__ p =
                reinterpret_cast<const float4*>(x + (size_t)b * NN * DD) + (size_t)row0 * (DD / 4);
            const int nvec = (row1 - row0) * (DD / 4);
            int i = threadIdx.x;
            for (; i + 768 < nvec; i += 1024) {
                float4 a  = p[i];
                float4 v1 = p[i + 256];
                float4 v2 = p[i + 512];
                float4 v3 = p[i + 768];
                s0 += (a.x + a.y) + (a.z + a.w);
                q0 += a.x * a.x + a.y * a.y + a.z * a.z + a.w * a.w;
                s1 += (v1.x + v1.y) + (v1.z + v1.w);
                q1 += v1.x * v1.x + v1.y * v1.y + v1.z * v1.z + v1.w * v1.w;
                s2 += (v2.x + v2.y) + (v2.z + v2.w);
                q2 += v2.x * v2.x + v2.y * v2.y + v2.z * v2.z + v2.w * v2.w;
                s3 += (v3.x + v3.y) + (v3.z + v3.w);
                q3 += v3.x * v3.x + v3.y * v3.y + v3.z * v3.z + v3.w * v3.w;
            }
            for (; i < nvec; i += 256) {
                float4 a = p[i];
                s0 += (a.x + a.y) + (a.z + a.w);
                q0 += a.x * a.x + a.y * a.y + a.z * a.z + a.w * a.w;
            }
        }
        float s  = (s0 + s1) + (s2 + s3);
        float ss = (q0 + q1) + (q2 + q3);

        #pragma unroll
        for (int off = 16; off > 0; off >>= 1) {
            s  += __shfl_xor_sync(0xFFFFFFFFu, s,  off);
            ss += __shfl_xor_sync(0xFFFFFFFFu, ss, off);
        }
        __shared__ float sh_s[8], sh_ss[8];
        const int wid = threadIdx.x >> 5;
        const int lid = threadIdx.x & 31;
        if (lid == 0) { sh_s[wid] = s; sh_ss[wid] = ss; }
        __syncthreads();
        if (wid != 0) return;
        s  = (lid < 8) ? sh_s[lid]  : 0.0f;
        ss = (lid < 8) ? sh_ss[lid] : 0.0f;
        #pragma unroll
        for (int off = 4; off > 0; off >>= 1) {
            s  += __shfl_xor_sync(0xFFFFFFFFu, s,  off);
            ss += __shfl_xor_sync(0xFFFFFFFFu, ss, off);
        }
        if (lid != 0) return;

        g_partial[b * CHUNKS + chunk] = make_float2(s, ss);
        __threadfence();
        const unsigned int old = atomicAdd(&g_count[b], 1u);
        if (old == CHUNKS - 1) {
            __threadfence();
            float fs = 0.0f, fss = 0.0f;
            #pragma unroll
            for (int i = 0; i < CHUNKS; i++) {
                float2 p = __ldcg(&g_partial[b * CHUNKS + i]);
                fs += p.x; fss += p.y;
            }
            const float denom = (float)len * (float)DD;
            const float mean  = fs / denom;
            const float var   = fmaxf(fss / denom - mean * mean, 0.0f);
            g_mi[b] = make_float2(mean, 1.0f / (sqrtf(var) + EPS));
            __threadfence();
            atomicExch(&g_count[b], FLAG_DONE);  // release flag
        }
        return;
    }

    // ---------------- Norm phase ----------------
    const int nb = bid - STATS_BLOCKS;
    const int b = nb >> 7;        // batch
    const int part = nb & (NPARTS - 1);
    const int len = lengths[b];
    const int base = part * ROWS_PER_NORM;
    const int r = base + (threadIdx.x >> 6);
    const int c = threadIdx.x & 63;

    float4* __restrict__ op = reinterpret_cast<float4*>(out);
    const size_t bidx = (size_t)b * NN * (DD / 4) + c;
    const float4 z = make_float4(0.0f, 0.0f, 0.0f, 0.0f);

    if (base >= len) {  // fully invalid: write-through zero-fill, no L2 allocate
        #pragma unroll
        for (int k = 0; k < 4; k++)
            __stwt(&op[bidx + (size_t)(r + 4 * k) * (DD / 4)], z);
        if (threadIdx.x == 0) {
            const unsigned int d = atomicAdd(&g_done[b], 1u);
            if (d == NPARTS - 1) {            // last norm block: re-arm protocol
                atomicExch(&g_count[b], 0u);
                atomicExch(&g_done[b], 0u);
            }
        }
        return;
    }

    // Gate on this batch's stats.
    if (threadIdx.x == 0) {
        while (*(volatile unsigned int*)&g_count[b] != FLAG_DONE) __nanosleep(32);
        __threadfence();
    }
    __syncthreads();

    const float2 mi = __ldcg(&g_mi[b]);   // L2 read: avoid stale L1 line
    const float mean = mi.x, inv = mi.y;
    const float4 w  = reinterpret_cast<const float4*>(weights)[c];
    const float4 bi = reinterpret_cast<const float4*>(biases)[c];

    if (base + ROWS_PER_NORM <= len) {  // fully valid: no per-row checks
        #pragma unroll
        for (int k = 0; k < 4; k++) {
            const size_t idx = bidx + (size_t)(r + 4 * k) * (DD / 4);
            const float4 v = reinterpret_cast<const float4*>(x)[idx];
            float4 o;
            o.x = (v.x - mean) * inv * w.x + bi.x;
            o.y = (v.y - mean) * inv * w.y + bi.y;
            o.z = (v.z - mean) * inv * w.z + bi.z;
            o.w = (v.w - mean) * inv * w.w + bi.w;
            __stwt(&op[idx], o);
        }
    } else {
        // Mixed block: per-row validity.
        #pragma unroll
        for (int k = 0; k < 4; k++) {
            const int row = r + 4 * k;
            const size_t idx = bidx + (size_t)row * (DD / 4);
            if (row < len) {
                const float4 v = reinterpret_cast<const float4*>(x)[idx];
                float4 o;
                o.x = (v.x - mean) * inv * w.x + bi.x;
                o.y = (v.y - mean) * inv * w.y + bi.y;
                o.z = (v.z - mean) * inv * w.z + bi.z;
                o.w = (v.w - mean) * inv * w.w + bi.w;
                __stwt(&op[idx], o);
            } else {
                __stwt(&op[idx], z);
            }
        }
    }

    if (threadIdx.x == 0) {
        const unsigned int d = atomicAdd(&g_done[b], 1u);
        if (d == NPARTS - 1) {                // last norm block: re-arm protocol
            atomicExch(&g_count[b], 0u);
            atomicExch(&g_done[b], 0u);
        }
    }
}

extern "C" void kernel_launch(void* const* d_in, const int* in_sizes, int n_in,
                              void* d_out, int out_size) {
    const float* x        = (const float*)d_in[0];
    const int*   lengths  = (const int*)d_in[1];
    const float* weights  = (const float*)d_in[2];
    const float* biases   = (const float*)d_in[3];
    float* out = (float*)d_out;

    fused_kernel<<<STATS_BLOCKS + BB * NPARTS, 256>>>(x, lengths, weights, biases, out);
}

// round 15
// speedup vs baseline: 1.0413x; 1.0028x over previous
#include <cuda_runtime.h>
#include <cuda_bf16.h>

#define BB 64
#define NN 2048
#define DD 256
#define EPS 1e-05f

#define CHUNKS 32
#define ROWS_PER_CHUNK (NN / CHUNKS)   // 64
#define ROWS_PER_NORM 16
#define NPARTS (NN / ROWS_PER_NORM)    // 128 norm blocks per batch
#define STATS_BLOCKS (BB * CHUNKS)     // 2048
#define FLAG_DONE (CHUNKS + 1)         // 33

// Owned-slot partials: no zeroing, no data races.
__device__ float2 g_partial[BB * CHUNKS];
__device__ float2 g_mi[BB];
// Protocol counters. Static-init 0; each launch restores them to 0 -> graph-safe.
__device__ unsigned int g_count[BB];
__device__ unsigned int g_done[BB];

// (256, 8): cap regs at 32 -> 8 blocks/SM resident (was 6 at regs=40).
__global__ __launch_bounds__(256, 8) void fused_kernel(const float* __restrict__ x,
                                                       const int* __restrict__ lengths,
                                                       const float* __restrict__ weights,
                                                       const float* __restrict__ biases,
                                                       float* __restrict__ out) {
    const int bid = blockIdx.x;

    if (bid < STATS_BLOCKS) {
        // ---------------- Stats phase ----------------
        const int b = bid >> 5;       // batch
        const int chunk = bid & 31;
        const int len = lengths[b];
        const int row0 = chunk * ROWS_PER_CHUNK;
        const int row1 = min(row0 + ROWS_PER_CHUNK, len);

        float s0 = 0.f, s1 = 0.f, s2 = 0.f, s3 = 0.f;
        float q0 = 0.f, q1 = 0.f, q2 = 0.f, q3 = 0.f;
        if (row1 > row0) {
            const float4* __restrict__ p =
                reinterpret_cast<const float4*>(x + (size_t)b * NN * DD) + (size_t)row0 * (DD / 4);
            const int nvec = (row1 - row0) * (DD / 4);
            int i = threadIdx.x;
            for (; i + 768 < nvec; i += 1024) {
                float4 a  = p[i];
                float4 v1 = p[i + 256];
                float4 v2 = p[i + 512];
                float4 v3 = p[i + 768];
                s0 += (a.x + a.y) + (a.z + a.w);
                q0 += a.x * a.x + a.y * a.y + a.z * a.z + a.w * a.w;
                s1 += (v1.x + v1.y) + (v1.z + v1.w);
                q1 += v1.x * v1.x + v1.y * v1.y + v1.z * v1.z + v1.w * v1.w;
                s2 += (v2.x + v2.y) + (v2.z + v2.w);
                q2 += v2.x * v2.x + v2.y * v2.y + v2.z * v2.z + v2.w * v2.w;
                s3 += (v3.x + v3.y) + (v3.z + v3.w);
                q3 += v3.x * v3.x + v3.y * v3.y + v3.z * v3.z + v3.w * v3.w;
            }
            for (; i < nvec; i += 256) {
                float4 a = p[i];
                s0 += (a.x + a.y) + (a.z + a.w);
                q0 += a.x * a.x + a.y * a.y + a.z * a.z + a.w * a.w;
            }
        }
        float s  = (s0 + s1) + (s2 + s3);
        float ss = (q0 + q1) + (q2 + q3);

        #pragma unroll
        for (int off = 16; off > 0; off >>= 1) {
            s  += __shfl_xor_sync(0xFFFFFFFFu, s,  off);
            ss += __shfl_xor_sync(0xFFFFFFFFu, ss, off);
        }
        __shared__ float sh_s[8], sh_ss[8];
        const int wid = threadIdx.x >> 5;
        const int lid = threadIdx.x & 31;
        if (lid == 0) { sh_s[wid] = s; sh_ss[wid] = ss; }
        __syncthreads();
        if (wid != 0) return;
        s  = (lid < 8) ? sh_s[lid]  : 0.0f;
        ss = (lid < 8) ? sh_ss[lid] : 0.0f;
        #pragma unroll
        for (int off = 4; off > 0; off >>= 1) {
            s  += __shfl_xor_sync(0xFFFFFFFFu, s,  off);
            ss += __shfl_xor_sync(0xFFFFFFFFu, ss, off);
        }
        if (lid != 0) return;

        g_partial[b * CHUNKS + chunk] = make_float2(s, ss);
        __threadfence();
        const unsigned int old = atomicAdd(&g_count[b], 1u);
        if (old == CHUNKS - 1) {
            __threadfence();
            float fs = 0.0f, fss = 0.0f;
            #pragma unroll
            for (int i = 0; i < CHUNKS; i++) {
                float2 p = __ldcg(&g_partial[b * CHUNKS + i]);
                fs += p.x; fss += p.y;
            }
            const float denom = (float)len * (float)DD;
            const float mean  = fs / denom;
            const float var   = fmaxf(fss / denom - mean * mean, 0.0f);
            g_mi[b] = make_float2(mean, 1.0f / (sqrtf(var) + EPS));
            __threadfence();
            atomicExch(&g_count[b], FLAG_DONE);  // release flag
        }
        return;
    }

    // ---------------- Norm phase ----------------
    const int nb = bid - STATS_BLOCKS;
    const int b = nb >> 7;        // batch
    const int part = nb & (NPARTS - 1);
    const int len = lengths[b];
    const int base = part * ROWS_PER_NORM;
    const int r = base + (threadIdx.x >> 6);
    const int c = threadIdx.x & 63;

    float4* __restrict__ op = reinterpret_cast<float4*>(out);
    const size_t bidx = (size_t)b * NN * (DD / 4) + c;
    const float4 z = make_float4(0.0f, 0.0f, 0.0f, 0.0f);

    if (base >= len) {  // fully invalid: pure streaming zero-fill
        #pragma unroll
        for (int k = 0; k < 4; k++)
            __stcs(&op[bidx + (size_t)(r + 4 * k) * (DD / 4)], z);
        if (threadIdx.x == 0) {
            const unsigned int d = atomicAdd(&g_done[b], 1u);
            if (d == NPARTS - 1) {            // last norm block: re-arm protocol
                atomicExch(&g_count[b], 0u);
                atomicExch(&g_done[b], 0u);
            }
        }
        return;
    }

    // Gate on this batch's stats.
    if (threadIdx.x == 0) {
        while (*(volatile unsigned int*)&g_count[b] != FLAG_DONE) __nanosleep(32);
        __threadfence();
    }
    __syncthreads();

    const float2 mi = __ldcg(&g_mi[b]);   // L2 read: avoid stale L1 line
    const float mean = mi.x, inv = mi.y;
    const float4 w  = reinterpret_cast<const float4*>(weights)[c];
    const float4 bi = reinterpret_cast<const float4*>(biases)[c];

    if (base + ROWS_PER_NORM <= len) {  // fully valid: no per-row checks
        #pragma unroll
        for (int k = 0; k < 4; k++) {
            const size_t idx = bidx + (size_t)(r + 4 * k) * (DD / 4);
            const float4 v = reinterpret_cast<const float4*>(x)[idx];
            float4 o;
            o.x = (v.x - mean) * inv * w.x + bi.x;
            o.y = (v.y - mean) * inv * w.y + bi.y;
            o.z = (v.z - mean) * inv * w.z + bi.z;
            o.w = (v.w - mean) * inv * w.w + bi.w;
            __stcs(&op[idx], o);
        }
    } else {
        // Mixed block: per-row validity.
        #pragma unroll
        for (int k = 0; k < 4; k++) {
            const int row = r + 4 * k;
            const size_t idx = bidx + (size_t)row * (DD / 4);
            if (row < len) {
                const float4 v = reinterpret_cast<const float4*>(x)[idx];
                float4 o;
                o.x = (v.x - mean) * inv * w.x + bi.x;
                o.y = (v.y - mean) * inv * w.y + bi.y;
                o.z = (v.z - mean) * inv * w.z + bi.z;
                o.w = (v.w - mean) * inv * w.w + bi.w;
                __stcs(&op[idx], o);
            } else {
                __stcs(&op[idx], z);
            }
        }
    }

    if (threadIdx.x == 0) {
        const unsigned int d = atomicAdd(&g_done[b], 1u);
        if (d == NPARTS - 1) {                // last norm block: re-arm protocol
            atomicExch(&g_count[b], 0u);
            atomicExch(&g_done[b], 0u);
        }
    }
}

extern "C" void kernel_launch(void* const* d_in, const int* in_sizes, int n_in,
                              void* d_out, int out_size) {
    const float* x        = (const float*)d_in[0];
    const int*   lengths  = (const int*)d_in[1];
    const float* weights  = (const float*)d_in[2];
    const float* biases   = (const float*)d_in[3];
    float* out = (float*)d_out;

    fused_kernel<<<STATS_BLOCKS + BB * NPARTS, 256>>>(x, lengths, weights, biases, out);
}

// round 16
// speedup vs baseline: 1.0517x; 1.0099x over previous
#include <cuda_runtime.h>
#include <cuda_bf16.h>

#define BB 64
#define NN 2048
#define DD 256
#define EPS 1e-05f

#define CHUNKS 32
#define ROWS_PER_NORM 16
#define NPARTS (NN / ROWS_PER_NORM)    // 128 norm blocks per batch
#define STATS_BLOCKS (BB * CHUNKS)     // 2048
#define FLAG_DONE (CHUNKS + 1)         // 33

// Owned-slot partials: no zeroing, no data races.
__device__ float2 g_partial[BB * CHUNKS];
__device__ float2 g_mi[BB];
// Protocol counters. Static-init 0; each launch restores them to 0 -> graph-safe.
__device__ unsigned int g_count[BB];
__device__ unsigned int g_done[BB];

// Strided-row stats chunk: chunk c owns rows {c, c+32, c+64, ...}.
// Every chunk of a batch has ~len/32 valid rows -> balanced blocks for any len.
// addr(i): vec i -> row k = i>>6 (64 float4 per row), col = i&63.
__device__ __forceinline__ float4 ld_strided(const float4* __restrict__ p,
                                             int chunk, int i) {
    const int k = i >> 6;
    const int col = i & 63;
    return p[((size_t)(chunk + (k << 5)) << 6) + col];
}

__global__ __launch_bounds__(256) void fused_kernel(const float* __restrict__ x,
                                                    const int* __restrict__ lengths,
                                                    const float* __restrict__ weights,
                                                    const float* __restrict__ biases,
                                                    float* __restrict__ out) {
    const int bid = blockIdx.x;

    if (bid < STATS_BLOCKS) {
        // ---------------- Stats phase (strided rows, balanced) ----------------
        const int b = bid >> 5;       // batch
        const int chunk = bid & 31;
        const int len = lengths[b];
        // rows chunk + 32k valid iff chunk + 32k < len
        const int nvalid = (len > chunk) ? ((len - chunk + 31) >> 5) : 0;
        const int nvec = nvalid << 6;   // 64 float4 per row

        float s0 = 0.f, s1 = 0.f, s2 = 0.f, s3 = 0.f;
        float q0 = 0.f, q1 = 0.f, q2 = 0.f, q3 = 0.f;
        if (nvec > 0) {
            const float4* __restrict__ p =
                reinterpret_cast<const float4*>(x + (size_t)b * NN * DD);
            int i = threadIdx.x;
            for (; i + 768 < nvec; i += 1024) {
                float4 a0 = ld_strided(p, chunk, i);
                float4 a1 = ld_strided(p, chunk, i + 256);
                float4 a2 = ld_strided(p, chunk, i + 512);
                float4 a3 = ld_strided(p, chunk, i + 768);
                s0 += (a0.x + a0.y) + (a0.z + a0.w);
                q0 += a0.x * a0.x + a0.y * a0.y + a0.z * a0.z + a0.w * a0.w;
                s1 += (a1.x + a1.y) + (a1.z + a1.w);
                q1 += a1.x * a1.x + a1.y * a1.y + a1.z * a1.z + a1.w * a1.w;
                s2 += (a2.x + a2.y) + (a2.z + a2.w);
                q2 += a2.x * a2.x + a2.y * a2.y + a2.z * a2.z + a2.w * a2.w;
                s3 += (a3.x + a3.y) + (a3.z + a3.w);
                q3 += a3.x * a3.x + a3.y * a3.y + a3.z * a3.z + a3.w * a3.w;
            }
            for (; i < nvec; i += 256) {
                float4 a = ld_strided(p, chunk, i);
                s0 += (a.x + a.y) + (a.z + a.w);
                q0 += a.x * a.x + a.y * a.y + a.z * a.z + a.w * a.w;
            }
        }
        float s  = (s0 + s1) + (s2 + s3);
        float ss = (q0 + q1) + (q2 + q3);

        #pragma unroll
        for (int off = 16; off > 0; off >>= 1) {
            s  += __shfl_xor_sync(0xFFFFFFFFu, s,  off);
            ss += __shfl_xor_sync(0xFFFFFFFFu, ss, off);
        }
        __shared__ float sh_s[8], sh_ss[8];
        const int wid = threadIdx.x >> 5;
        const int lid = threadIdx.x & 31;
        if (lid == 0) { sh_s[wid] = s; sh_ss[wid] = ss; }
        __syncthreads();
        if (wid != 0) return;
        s  = (lid < 8) ? sh_s[lid]  : 0.0f;
        ss = (lid < 8) ? sh_ss[lid] : 0.0f;
        #pragma unroll
        for (int off = 4; off > 0; off >>= 1) {
            s  += __shfl_xor_sync(0xFFFFFFFFu, s,  off);
            ss += __shfl_xor_sync(0xFFFFFFFFu, ss, off);
        }
        if (lid != 0) return;

        g_partial[b * CHUNKS + chunk] = make_float2(s, ss);
        __threadfence();
        const unsigned int old = atomicAdd(&g_count[b], 1u);
        if (old == CHUNKS - 1) {
            __threadfence();
            float fs = 0.0f, fss = 0.0f;
            #pragma unroll
            for (int i = 0; i < CHUNKS; i++) {
                float2 p2 = __ldcg(&g_partial[b * CHUNKS + i]);
                fs += p2.x; fss += p2.y;
            }
            const float denom = (float)len * (float)DD;
            const float mean  = fs / denom;
            const float var   = fmaxf(fss / denom - mean * mean, 0.0f);
            g_mi[b] = make_float2(mean, 1.0f / (sqrtf(var) + EPS));
            __threadfence();
            atomicExch(&g_count[b], FLAG_DONE);  // release flag
        }
        return;
    }

    // ---------------- Norm phase ----------------
    const int nb = bid - STATS_BLOCKS;
    const int b = nb >> 7;        // batch
    const int part = nb & (NPARTS - 1);
    const int len = lengths[b];
    const int base = part * ROWS_PER_NORM;
    const int r = base + (threadIdx.x >> 6);
    const int c = threadIdx.x & 63;

    float4* __restrict__ op = reinterpret_cast<float4*>(out);
    const size_t bidx = (size_t)b * NN * (DD / 4) + c;
    const float4 z = make_float4(0.0f, 0.0f, 0.0f, 0.0f);

    if (base >= len) {  // fully invalid: pure streaming zero-fill
        #pragma unroll
        for (int k = 0; k < 4; k++)
            __stcs(&op[bidx + (size_t)(r + 4 * k) * (DD / 4)], z);
        if (threadIdx.x == 0) {
            const unsigned int d = atomicAdd(&g_done[b], 1u);
            if (d == NPARTS - 1) {            // last norm block: re-arm protocol
                atomicExch(&g_count[b], 0u);
                atomicExch(&g_done[b], 0u);
            }
        }
        return;
    }

    // Gate on this batch's stats.
    if (threadIdx.x == 0) {
        while (*(volatile unsigned int*)&g_count[b] != FLAG_DONE) __nanosleep(32);
        __threadfence();
    }
    __syncthreads();

    const float2 mi = __ldcg(&g_mi[b]);   // L2 read: avoid stale L1 line
    const float mean = mi.x, inv = mi.y;
    const float4 w  = reinterpret_cast<const float4*>(weights)[c];
    const float4 bi = reinterpret_cast<const float4*>(biases)[c];

    if (base + ROWS_PER_NORM <= len) {  // fully valid: no per-row checks
        #pragma unroll
        for (int k = 0; k < 4; k++) {
            const size_t idx = bidx + (size_t)(r + 4 * k) * (DD / 4);
            const float4 v = reinterpret_cast<const float4*>(x)[idx];
            float4 o;
            o.x = (v.x - mean) * inv * w.x + bi.x;
            o.y = (v.y - mean) * inv * w.y + bi.y;
            o.z = (v.z - mean) * inv * w.z + bi.z;
            o.w = (v.w - mean) * inv * w.w + bi.w;
            __stcs(&op[idx], o);
        }
    } else {
        // Mixed block: per-row validity.
        #pragma unroll
        for (int k = 0; k < 4; k++) {
            const int row = r + 4 * k;
            const size_t idx = bidx + (size_t)row * (DD / 4);
            if (row < len) {
                const float4 v = reinterpret_cast<const float4*>(x)[idx];
                float4 o;
                o.x = (v.x - mean) * inv * w.x + bi.x;
                o.y = (v.y - mean) * inv * w.y + bi.y;
                o.z = (v.z - mean) * inv * w.z + bi.z;
                o.w = (v.w - mean) * inv * w.w + bi.w;
                __stcs(&op[idx], o);
            } else {
                __stcs(&op[idx], z);
            }
        }
    }

    if (threadIdx.x == 0) {
        const unsigned int d = atomicAdd(&g_done[b], 1u);
        if (d == NPARTS - 1) {                // last norm block: re-arm protocol
            atomicExch(&g_count[b], 0u);
            atomicExch(&g_done[b], 0u);
        }
    }
}

extern "C" void kernel_launch(void* const* d_in, const int* in_sizes, int n_in,
                              void* d_out, int out_size) {
    const float* x        = (const float*)d_in[0];
    const int*   lengths  = (const int*)d_in[1];
    const float* weights  = (const float*)d_in[2];
    const float* biases   = (const float*)d_in[3];
    float* out = (float*)d_out;

    fused_kernel<<<STATS_BLOCKS + BB * NPARTS, 256>>>(x, lengths, weights, biases, out);
}